// round 16
// baseline (speedup 1.0000x reference)
#include <cuda_runtime.h>
#include <math.h>

#define BATCH 8
#define SEQ   2048
#define DIM   1024
#define HEAD  64
#define MROWS (BATCH * SEQ)      // 16384
#define BQ  64
#define TK  64
#define NQT2 (SEQ / BQ)          // 32
#define NEG_BIG (-3.0e38f)

// proj dynamic smem layout (words)
#define XS_WORDS (2 * 64 * 36)
#define WS_WORDS (2 * 3 * 32 * 72)
#define PROJ_SMEM_BYTES ((XS_WORDS + WS_WORDS) * 4)   // 73728

// attn dynamic smem layout (words): Ks[2][64][68] then Vs[64][72]
#define AKS_WORDS (64 * 68)
#define AVS_OFF   (2 * AKS_WORDS)
#define ATTN_SMEM_BYTES ((2 * AKS_WORDS + 64 * 72) * 4)   // 53248

// Scratch (no allocation allowed -> device globals)
__device__ unsigned g_Qt[MROWS * HEAD];   // Q as tf32 bits, pre-scaled by 1/8
__device__ unsigned g_Kt[MROWS * HEAD];   // K as tf32 bits
__device__ unsigned g_Vt[MROWS * HEAD];   // V as tf32 bits
__device__ unsigned g_Wt[3][DIM * HEAD];  // W pre-converted to tf32 bits (q,k,v)
__device__ float g_Op[2][MROWS * HEAD];   // split-K partial O (unnormalized)
__device__ float g_m[2][MROWS];           // split-K partial row max
__device__ float g_l[2][MROWS];           // split-K partial row sum

// ---------------- tf32 / async helpers ----------------
__device__ __forceinline__ unsigned f2tf(float x) {
    unsigned r;
    asm("cvt.rna.tf32.f32 %0, %1;" : "=r"(r) : "f"(x));
    return r;
}

__device__ __forceinline__ void mma_tf32(float d[4], const unsigned a[4], const unsigned b[2]) {
    asm("mma.sync.aligned.m16n8k8.row.col.f32.tf32.tf32.f32 "
        "{%0,%1,%2,%3}, {%4,%5,%6,%7}, {%8,%9}, {%0,%1,%2,%3};"
        : "+f"(d[0]), "+f"(d[1]), "+f"(d[2]), "+f"(d[3])
        : "r"(a[0]), "r"(a[1]), "r"(a[2]), "r"(a[3]), "r"(b[0]), "r"(b[1]));
}

__device__ __forceinline__ void cp16(void* smem, const void* gptr) {
    unsigned s = (unsigned)__cvta_generic_to_shared(smem);
    asm volatile("cp.async.cg.shared.global [%0], [%1], 16;" :: "r"(s), "l"(gptr));
}
#define CP_COMMIT() asm volatile("cp.async.commit_group;")
#define CP_WAIT2()  asm volatile("cp.async.wait_group 2;")
#define CP_WAIT1()  asm volatile("cp.async.wait_group 1;")
#define CP_WAIT0()  asm volatile("cp.async.wait_group 0;")

// ---------------------------------------------------------------------------
// Kernel 0: pre-convert the three W matrices to tf32 bits.
// ---------------------------------------------------------------------------
__global__ __launch_bounds__(256)
void wconv_kernel(const float* __restrict__ Wq,
                  const float* __restrict__ Wk,
                  const float* __restrict__ Wv)
{
    const int t = blockIdx.x * 256 + threadIdx.x;   // 0 .. 3*16384-1
    const int w = t >> 14;
    const int e = t & 16383;
    const float* W = (w == 0) ? Wq : (w == 1) ? Wk : Wv;
    float4 v = *(const float4*)&W[e * 4];
    uint4 u;
    u.x = f2tf(v.x); u.y = f2tf(v.y); u.z = f2tf(v.z); u.w = f2tf(v.w);
    *(uint4*)&g_Wt[w][e * 4] = u;
}

// ---------------------------------------------------------------------------
// Kernel 1: FUSED QKV projection, tf32 MMA + cp.async 2-stage pipeline.
// k-chunk 32 (unchanged from R14 — proven at 120.8us).
// ---------------------------------------------------------------------------
__global__ __launch_bounds__(256)
void proj_kernel(const float* __restrict__ x)
{
    extern __shared__ unsigned psm[];
    float    (*Xs)[64][36]     = (float(*)[64][36])psm;
    unsigned (*Ws)[3][32][72]  = (unsigned(*)[3][32][72])(psm + XS_WORDS);

    const int tid  = threadIdx.x;
    const int warp = tid >> 5;
    const int lane = tid & 31;
    const int g    = lane >> 2;
    const int c    = lane & 3;
    const int mrow = (warp >> 1) * 16;
    const int nh   = warp & 1;
    const int row0 = blockIdx.x * 64;

    const int xr0 = tid >> 3,          xs0 = tid & 7;
    const int xr1 = (tid + 256) >> 3,  xs1 = tid & 7;
    const int wr0 = tid >> 4,          ws0 = tid & 15;
    const int wr1 = (tid + 256) >> 4,  ws1 = tid & 15;

    float acc[3][4][4];
    #pragma unroll
    for (int w = 0; w < 3; w++)
        #pragma unroll
        for (int nt = 0; nt < 4; nt++)
            #pragma unroll
            for (int j = 0; j < 4; j++) acc[w][nt][j] = 0.0f;

    {
        cp16(&Xs[0][xr0][xs0 * 4], &x[(size_t)(row0 + xr0) * DIM + xs0 * 4]);
        cp16(&Xs[0][xr1][xs1 * 4], &x[(size_t)(row0 + xr1) * DIM + xs1 * 4]);
        #pragma unroll
        for (int w = 0; w < 3; w++) {
            cp16(&Ws[0][w][wr0][ws0 * 4], &g_Wt[w][(size_t)wr0 * HEAD + ws0 * 4]);
            cp16(&Ws[0][w][wr1][ws1 * 4], &g_Wt[w][(size_t)wr1 * HEAD + ws1 * 4]);
        }
        CP_COMMIT();
    }

    #pragma unroll 1
    for (int ck = 0; ck < 32; ck++) {
        const int st = ck & 1;
        if (ck < 31) {
            const int k0 = (ck + 1) * 32;
            const int sn = st ^ 1;
            cp16(&Xs[sn][xr0][xs0 * 4], &x[(size_t)(row0 + xr0) * DIM + k0 + xs0 * 4]);
            cp16(&Xs[sn][xr1][xs1 * 4], &x[(size_t)(row0 + xr1) * DIM + k0 + xs1 * 4]);
            #pragma unroll
            for (int w = 0; w < 3; w++) {
                cp16(&Ws[sn][w][wr0][ws0 * 4], &g_Wt[w][(size_t)(k0 + wr0) * HEAD + ws0 * 4]);
                cp16(&Ws[sn][w][wr1][ws1 * 4], &g_Wt[w][(size_t)(k0 + wr1) * HEAD + ws1 * 4]);
            }
            CP_COMMIT();
            CP_WAIT1();
        } else {
            CP_WAIT0();
        }
        __syncthreads();

        #pragma unroll
        for (int ks = 0; ks < 4; ks++) {
            unsigned a[4];
            a[0] = f2tf(Xs[st][mrow + g][ks * 8 + c]);
            a[1] = f2tf(Xs[st][mrow + g + 8][ks * 8 + c]);
            a[2] = f2tf(Xs[st][mrow + g][ks * 8 + c + 4]);
            a[3] = f2tf(Xs[st][mrow + g + 8][ks * 8 + c + 4]);
            #pragma unroll
            for (int w = 0; w < 3; w++) {
                #pragma unroll
                for (int nt = 0; nt < 4; nt++) {
                    const int ntg = nh * 4 + nt;
                    unsigned b[2];
                    b[0] = Ws[st][w][ks * 8 + c][ntg * 8 + g];
                    b[1] = Ws[st][w][ks * 8 + c + 4][ntg * 8 + g];
                    mma_tf32(acc[w][nt], a, b);
                }
            }
        }
        __syncthreads();
    }

    #pragma unroll
    for (int w = 0; w < 3; w++) {
        unsigned* out = (w == 0) ? g_Qt : (w == 1) ? g_Kt : g_Vt;
        const float sc = (w == 0) ? 0.125f : 1.0f;
        #pragma unroll
        for (int nt = 0; nt < 4; nt++) {
            const int ntg = nh * 4 + nt;
            uint2 lo; lo.x = f2tf(acc[w][nt][0] * sc); lo.y = f2tf(acc[w][nt][1] * sc);
            uint2 hi; hi.x = f2tf(acc[w][nt][2] * sc); hi.y = f2tf(acc[w][nt][3] * sc);
            *(uint2*)&out[(size_t)(row0 + mrow + g)     * HEAD + ntg * 8 + 2 * c] = lo;
            *(uint2*)&out[(size_t)(row0 + mrow + g + 8) * HEAD + ntg * 8 + 2 * c] = hi;
        }
    }
}

// ---------------------------------------------------------------------------
// Kernel 2: fused causal flash attention v7 — K double-buffered, V issued
// early (latency hidden behind scores+softmax), P reuses current K buffer.
// 53KB dynamic smem keeps residency; 3 barriers/tile; numerics bit-identical.
// ---------------------------------------------------------------------------
__global__ __launch_bounds__(128)
void attn_kernel()
{
    extern __shared__ unsigned dsm[];
    unsigned (*KsBuf)[64][68] = (unsigned(*)[64][68])dsm;      // [2][64][68]
    unsigned (*Vs)[72]        = (unsigned(*)[72])(dsm + AVS_OFF);

    const int tid  = threadIdx.x;
    const int warp = tid >> 5;
    const int lane = tid & 31;
    const int g    = lane >> 2;
    const int c    = lane & 3;

    const int qt   = (NQT2 - 1) - (blockIdx.x >> 1);   // heavy-first
    const int half = blockIdx.x & 1;
    const int b    = blockIdx.y;
    const size_t base = (size_t)b * SEQ * HEAD;
    const int qg0   = qt * BQ;
    const int qrow0 = qg0 + 16 * warp;

    const int nkt  = qt + 1;
    const int h    = (nkt + 1) >> 1;
    const int ktlo = half ? h : 0;
    const int kthi = half ? nkt : h;

    const unsigned* Qsrc = g_Qt + base;
    const unsigned* Ksrc = g_Kt + base;
    const unsigned* Vsrc = g_Vt + base;

    const int lkey = tid >> 4;   // load rows lkey + 8*it
    const int ld4  = tid & 15;

    // Q A-fragments: direct bit loads (pre-scaled, pre-converted)
    unsigned Qf[8][4];
    #pragma unroll
    for (int ks = 0; ks < 8; ks++) {
        Qf[ks][0] = Qsrc[(size_t)(qrow0 + g)     * HEAD + ks * 8 + c];
        Qf[ks][1] = Qsrc[(size_t)(qrow0 + g + 8) * HEAD + ks * 8 + c];
        Qf[ks][2] = Qsrc[(size_t)(qrow0 + g)     * HEAD + ks * 8 + c + 4];
        Qf[ks][3] = Qsrc[(size_t)(qrow0 + g + 8) * HEAD + ks * 8 + c + 4];
    }

    float O[8][4];
    #pragma unroll
    for (int nt = 0; nt < 8; nt++)
        #pragma unroll
        for (int j = 0; j < 4; j++) O[nt][j] = 0.0f;
    float mrun[2] = { NEG_BIG, NEG_BIG };
    float lrun[2] = { 0.0f, 0.0f };

    // prologue: stream first K tile
    if (ktlo < kthi) {
        const int k0p = ktlo * TK;
        #pragma unroll
        for (int it = 0; it < 8; it++) {
            const int key = lkey + it * 8;
            cp16(&KsBuf[ktlo & 1][key][ld4 * 4], &Ksrc[(size_t)(k0p + key) * HEAD + ld4 * 4]);
        }
        CP_COMMIT();
    }

    #pragma unroll 1
    for (int kt = ktlo; kt < kthi; kt++) {
        const int st = kt & 1;
        const int k0 = kt * TK;
        const bool more = (kt + 1 < kthi);

        __syncthreads();   // sync_a: all warps done with Vs + P(Ks[st^1 prev]) of kt-1

        // issue V(kt) — consumed only after scores+softmax (latency hidden)
        #pragma unroll
        for (int it = 0; it < 8; it++) {
            const int key = lkey + it * 8;
            cp16(&Vs[key][ld4 * 4], &Vsrc[(size_t)(k0 + key) * HEAD + ld4 * 4]);
        }
        CP_COMMIT();

        // issue K(kt+1) into the other buffer
        if (more) {
            const int k0n = k0 + TK;
            #pragma unroll
            for (int it = 0; it < 8; it++) {
                const int key = lkey + it * 8;
                cp16(&KsBuf[st ^ 1][key][ld4 * 4], &Ksrc[(size_t)(k0n + key) * HEAD + ld4 * 4]);
            }
            CP_COMMIT();
            CP_WAIT2();    // K(kt) done (V(kt), K(kt+1) still in flight)
        } else {
            CP_WAIT1();    // K(kt) done (V(kt) still in flight)
        }
        __syncthreads();   // sync_b: K(kt) visible to all warps

        unsigned (*Ks)[68] = KsBuf[st];

        // ---- scores ----
        float S[8][4];
        #pragma unroll
        for (int nt = 0; nt < 8; nt++)
            #pragma unroll
            for (int j = 0; j < 4; j++) S[nt][j] = 0.0f;

        #pragma unroll
        for (int ks = 0; ks < 8; ks++) {
            #pragma unroll
            for (int nt = 0; nt < 8; nt++) {
                unsigned bf[2];
                bf[0] = Ks[nt * 8 + g][ks * 8 + c];
                bf[1] = Ks[nt * 8 + g][ks * 8 + c + 4];
                mma_tf32(S[nt], Qf[ks], bf);
            }
        }

        // causal mask (diagonal tile)
        if (kt == qt) {
            #pragma unroll
            for (int nt = 0; nt < 8; nt++)
                #pragma unroll
                for (int j = 0; j < 4; j++) {
                    const int col = k0 + nt * 8 + 2 * c + (j & 1);
                    const int row = qrow0 + g + ((j >= 2) ? 8 : 0);
                    if (col > row) S[nt][j] = NEG_BIG;
                }
        }

        // ---- online softmax (rows g, g+8) ----
        float mx0 = NEG_BIG, mx1 = NEG_BIG;
        #pragma unroll
        for (int nt = 0; nt < 8; nt++) {
            mx0 = fmaxf(mx0, fmaxf(S[nt][0], S[nt][1]));
            mx1 = fmaxf(mx1, fmaxf(S[nt][2], S[nt][3]));
        }
        mx0 = fmaxf(mx0, __shfl_xor_sync(0xffffffffu, mx0, 1));
        mx0 = fmaxf(mx0, __shfl_xor_sync(0xffffffffu, mx0, 2));
        mx1 = fmaxf(mx1, __shfl_xor_sync(0xffffffffu, mx1, 1));
        mx1 = fmaxf(mx1, __shfl_xor_sync(0xffffffffu, mx1, 2));

        const float mn0 = fmaxf(mrun[0], mx0);
        const float mn1 = fmaxf(mrun[1], mx1);
        const float al0 = __expf(mrun[0] - mn0);
        const float al1 = __expf(mrun[1] - mn1);

        float ps0 = 0.0f, ps1 = 0.0f;
        #pragma unroll
        for (int nt = 0; nt < 8; nt++) {
            float p0 = __uint_as_float(f2tf(__expf(S[nt][0] - mn0)));
            float p1 = __uint_as_float(f2tf(__expf(S[nt][1] - mn0)));
            float p2 = __uint_as_float(f2tf(__expf(S[nt][2] - mn1)));
            float p3 = __uint_as_float(f2tf(__expf(S[nt][3] - mn1)));
            S[nt][0] = p0; S[nt][1] = p1; S[nt][2] = p2; S[nt][3] = p3;
            ps0 += p0 + p1;
            ps1 += p2 + p3;
        }
        ps0 += __shfl_xor_sync(0xffffffffu, ps0, 1);
        ps0 += __shfl_xor_sync(0xffffffffu, ps0, 2);
        ps1 += __shfl_xor_sync(0xffffffffu, ps1, 1);
        ps1 += __shfl_xor_sync(0xffffffffu, ps1, 2);

        lrun[0] = lrun[0] * al0 + ps0;
        lrun[1] = lrun[1] * al1 + ps1;
        mrun[0] = mn0;
        mrun[1] = mn1;
        #pragma unroll
        for (int nt = 0; nt < 8; nt++) {
            O[nt][0] *= al0; O[nt][1] *= al0;
            O[nt][2] *= al1; O[nt][3] *= al1;
        }

        // wait for V(kt); K(kt+1) may still be in flight
        if (more) CP_WAIT1(); else CP_WAIT0();
        __syncthreads();   // sync_v: V visible; all warps done reading Ks[st] for scores

        // publish P into Ks[st] (warp-private rows; dead for scores now)
        #pragma unroll
        for (int nt = 0; nt < 8; nt++) {
            uint2 lo; lo.x = __float_as_uint(S[nt][0]); lo.y = __float_as_uint(S[nt][1]);
            uint2 hi; hi.x = __float_as_uint(S[nt][2]); hi.y = __float_as_uint(S[nt][3]);
            *(uint2*)&Ks[16 * warp + g][nt * 8 + 2 * c]     = lo;
            *(uint2*)&Ks[16 * warp + g + 8][nt * 8 + 2 * c] = hi;
        }
        __syncwarp();

        // ---- PV ----
        #pragma unroll
        for (int kp = 0; kp < 8; kp++) {
            unsigned a[4];
            a[0] = Ks[16 * warp + g][kp * 8 + c];
            a[1] = Ks[16 * warp + g + 8][kp * 8 + c];
            a[2] = Ks[16 * warp + g][kp * 8 + c + 4];
            a[3] = Ks[16 * warp + g + 8][kp * 8 + c + 4];
            #pragma unroll
            for (int nt = 0; nt < 8; nt++) {
                unsigned bf[2];
                bf[0] = Vs[kp * 8 + c][nt * 8 + g];
                bf[1] = Vs[kp * 8 + c + 4][nt * 8 + g];
                mma_tf32(O[nt], a, bf);
            }
        }
    }

    // epilogue: write unnormalized partials + m,l for this half
    float* Op = g_Op[half];
    #pragma unroll
    for (int nt = 0; nt < 8; nt++) {
        float2 lo; lo.x = O[nt][0]; lo.y = O[nt][1];
        float2 hi; hi.x = O[nt][2]; hi.y = O[nt][3];
        *(float2*)&Op[base + (size_t)(qrow0 + g)     * HEAD + nt * 8 + 2 * c] = lo;
        *(float2*)&Op[base + (size_t)(qrow0 + g + 8) * HEAD + nt * 8 + 2 * c] = hi;
    }
    if (c == 0) {
        const int rg = b * SEQ + qrow0 + g;
        g_m[half][rg]     = mrun[0];
        g_l[half][rg]     = lrun[0];
        g_m[half][rg + 8] = mrun[1];
        g_l[half][rg + 8] = lrun[1];
    }
}

// ---------------------------------------------------------------------------
// Kernel 3: split-K combine (separate kernel — R14 configuration).
// ---------------------------------------------------------------------------
__global__ __launch_bounds__(128)
void combine_kernel(float* __restrict__ z)
{
    const int tid  = threadIdx.x;
    const int r    = blockIdx.x * 32 + (tid >> 2);
    const int part = tid & 3;

    const float m0 = g_m[0][r], m1 = g_m[1][r];
    const float l0 = g_l[0][r], l1 = g_l[1][r];
    const float M  = fmaxf(m0, m1);
    const float w0 = __expf(m0 - M);
    const float w1 = __expf(m1 - M);
    const float inv = 1.0f / (l0 * w0 + l1 * w1);

    const size_t rb = (size_t)r * HEAD + part * 16;
    #pragma unroll
    for (int d4 = 0; d4 < 4; d4++) {
        float4 a  = *(const float4*)&g_Op[0][rb + d4 * 4];
        float4 bq = *(const float4*)&g_Op[1][rb + d4 * 4];
        float4 o;
        o.x = (a.x * w0 + bq.x * w1) * inv;
        o.y = (a.y * w0 + bq.y * w1) * inv;
        o.z = (a.z * w0 + bq.z * w1) * inv;
        o.w = (a.w * w0 + bq.w * w1) * inv;
        *(float4*)&z[rb + d4 * 4] = o;
    }
}

// ---------------------------------------------------------------------------
extern "C" void kernel_launch(void* const* d_in, const int* in_sizes, int n_in,
                              void* d_out, int out_size)
{
    const float* x  = (const float*)d_in[0];
    const float* Wk = (const float*)d_in[1];
    const float* Wq = (const float*)d_in[2];
    const float* Wv = (const float*)d_in[3];
    float* z = (float*)d_out;
    (void)in_sizes; (void)n_in; (void)out_size;

    // opt-in to >48KB dynamic smem (idempotent; capture-legal)
    cudaFuncSetAttribute(proj_kernel,
                         cudaFuncAttributeMaxDynamicSharedMemorySize,
                         PROJ_SMEM_BYTES);
    cudaFuncSetAttribute(attn_kernel,
                         cudaFuncAttributeMaxDynamicSharedMemorySize,
                         ATTN_SMEM_BYTES);

    wconv_kernel<<<192, 256>>>(Wq, Wk, Wv);

    proj_kernel<<<MROWS / 64, 256, PROJ_SMEM_BYTES>>>(x);

    dim3 agrid(2 * NQT2, BATCH);
    attn_kernel<<<agrid, 128, ATTN_SMEM_BYTES>>>();

    combine_kernel<<<MROWS / 32, 128>>>(z);
}

// round 17
// speedup vs baseline: 1.2075x; 1.2075x over previous
#include <cuda_runtime.h>
#include <math.h>

#define BATCH 8
#define SEQ   2048
#define DIM   1024
#define HEAD  64
#define MROWS (BATCH * SEQ)      // 16384
#define BQ  64
#define TK  64
#define NQT2 (SEQ / BQ)          // 32
#define NEG_BIG (-3.0e38f)

// proj dynamic smem layout (words)
// Xs: 2 stages x 64 rows x 36 (raw fp32)
// WsF: 2 stages x 96 tiles (3w x 4kb x 8nb) x 64 words (fragment-major tf32)
#define XS_WORDS  (2 * 64 * 36)              // 4608
#define WSF_STAGE (96 * 64)                  // 6144 words per stage
#define PROJ_SMEM_BYTES ((XS_WORDS + 2 * WSF_STAGE) * 4)   // 67584

// Scratch (no allocation allowed -> device globals)
__device__ unsigned g_Qt[MROWS * HEAD];   // Q as tf32 bits, pre-scaled by 1/8
__device__ unsigned g_Kt[MROWS * HEAD];   // K as tf32 bits
__device__ unsigned g_Vt[MROWS * HEAD];   // V as tf32 bits
__device__ unsigned g_Wf[3][DIM * HEAD];  // W tf32 bits, FRAGMENT-MAJOR tiles
__device__ float g_Op[2][MROWS * HEAD];   // split-K partial O (unnormalized)
__device__ float g_m[2][MROWS];           // split-K partial row max
__device__ float g_l[2][MROWS];           // split-K partial row sum

// ---------------- tf32 / async helpers ----------------
__device__ __forceinline__ unsigned f2tf(float x) {
    unsigned r;
    asm("cvt.rna.tf32.f32 %0, %1;" : "=r"(r) : "f"(x));
    return r;
}

__device__ __forceinline__ void mma_tf32(float d[4], const unsigned a[4], const unsigned b[2]) {
    asm("mma.sync.aligned.m16n8k8.row.col.f32.tf32.tf32.f32 "
        "{%0,%1,%2,%3}, {%4,%5,%6,%7}, {%8,%9}, {%0,%1,%2,%3};"
        : "+f"(d[0]), "+f"(d[1]), "+f"(d[2]), "+f"(d[3])
        : "r"(a[0]), "r"(a[1]), "r"(a[2]), "r"(a[3]), "r"(b[0]), "r"(b[1]));
}

__device__ __forceinline__ void cp16(void* smem, const void* gptr) {
    unsigned s = (unsigned)__cvta_generic_to_shared(smem);
    asm volatile("cp.async.cg.shared.global [%0], [%1], 16;" :: "r"(s), "l"(gptr));
}
#define CP_COMMIT() asm volatile("cp.async.commit_group;")
#define CP_WAIT1()  asm volatile("cp.async.wait_group 1;")
#define CP_WAIT0()  asm volatile("cp.async.wait_group 0;")

// ---------------------------------------------------------------------------
// Kernel 0: pre-convert W to tf32 bits in FRAGMENT-MAJOR tile layout.
// Tile (kb, nb) = 8k x 8n.  Within a tile: word index = lane*2 + slot,
// lane = g*4 + c, slot 0 -> W[kb*8+c][nb*8+g], slot 1 -> W[kb*8+c+4][nb*8+g].
// Output writes are fully coalesced (t maps linearly to the output index).
// ---------------------------------------------------------------------------
__global__ __launch_bounds__(256)
void wconv_kernel(const float* __restrict__ Wq,
                  const float* __restrict__ Wk,
                  const float* __restrict__ Wv)
{
    const int t = blockIdx.x * 256 + threadIdx.x;   // 0 .. 3*65536-1
    const int w   = t >> 16;
    const int rem = t & 65535;
    const int tile_lin = rem >> 6;     // kb*8 + nb  (0..1023)
    const int lane2    = rem & 63;
    const int lane = lane2 >> 1;
    const int slot = lane2 & 1;
    const int g = lane >> 2;
    const int c = lane & 3;
    const int kb = tile_lin >> 3;
    const int nb = tile_lin & 7;
    const int k = kb * 8 + c + slot * 4;
    const int n = nb * 8 + g;
    const float* W = (w == 0) ? Wq : (w == 1) ? Wk : Wv;
    g_Wf[w][rem + 0] = f2tf(W[k * HEAD + n]);
    (void)0;
}

// ---------------------------------------------------------------------------
// Kernel 1: FUSED QKV projection, tf32 MMA + cp.async 2-stage pipeline.
// k-chunk 32.  W consumed from fragment-major smem via single LDS.64 per
// b-fragment (was 2x LDS.32).  Numerics bit-identical to R14.
// ---------------------------------------------------------------------------
__global__ __launch_bounds__(256)
void proj_kernel(const float* __restrict__ x)
{
    extern __shared__ unsigned psm[];
    float    (*Xs)[64][36] = (float(*)[64][36])psm;       // [stage][row][k]
    unsigned* WsF          = psm + XS_WORDS;              // [stage][96 tiles][64]

    const int tid  = threadIdx.x;
    const int warp = tid >> 5;
    const int lane = tid & 31;
    const int g    = lane >> 2;   // 0..7
    const int c    = lane & 3;    // 0..3
    const int mrow = (warp >> 1) * 16;
    const int nh   = warp & 1;
    const int row0 = blockIdx.x * 64;

    // per-thread load indices: X 2 float4; W 6 cp16 (1536 total / 256 thr)
    const int xr0 = tid >> 3,          xs0 = tid & 7;
    const int xr1 = (tid + 256) >> 3,  xs1 = tid & 7;

    float acc[3][4][4];
    #pragma unroll
    for (int w = 0; w < 3; w++)
        #pragma unroll
        for (int nt = 0; nt < 4; nt++)
            #pragma unroll
            for (int j = 0; j < 4; j++) acc[w][nt][j] = 0.0f;

    // W tile copy helper indices: j = tid + i*256, tile = j>>4, part = j&15
    // tile (0..95) -> w = tile/32, tl = tile%32, kbl = tl>>3, nb = tl&7
    // ---- prologue: chunk 0 into stage 0 ----
    {
        cp16(&Xs[0][xr0][xs0 * 4], &x[(size_t)(row0 + xr0) * DIM + xs0 * 4]);
        cp16(&Xs[0][xr1][xs1 * 4], &x[(size_t)(row0 + xr1) * DIM + xs1 * 4]);
        #pragma unroll
        for (int i = 0; i < 6; i++) {
            const int j    = tid + i * 256;
            const int tile = j >> 4;
            const int part = j & 15;
            const int w    = tile >> 5;
            const int tl   = tile & 31;
            const int kbl  = tl >> 3;
            const int nb   = tl & 7;
            cp16(&WsF[tile * 64 + part * 4],
                 &g_Wf[w][((0 + kbl) * 8 + nb) * 64 + part * 4]);
        }
        CP_COMMIT();
    }

    #pragma unroll 1
    for (int ck = 0; ck < 32; ck++) {
        const int st = ck & 1;
        if (ck < 31) {
            const int k0   = (ck + 1) * 32;
            const int kbb  = (ck + 1) * 4;
            const int sn   = st ^ 1;
            cp16(&Xs[sn][xr0][xs0 * 4], &x[(size_t)(row0 + xr0) * DIM + k0 + xs0 * 4]);
            cp16(&Xs[sn][xr1][xs1 * 4], &x[(size_t)(row0 + xr1) * DIM + k0 + xs1 * 4]);
            #pragma unroll
            for (int i = 0; i < 6; i++) {
                const int j    = tid + i * 256;
                const int tile = j >> 4;
                const int part = j & 15;
                const int w    = tile >> 5;
                const int tl   = tile & 31;
                const int kbl  = tl >> 3;
                const int nb   = tl & 7;
                cp16(&WsF[sn * WSF_STAGE + tile * 64 + part * 4],
                     &g_Wf[w][((kbb + kbl) * 8 + nb) * 64 + part * 4]);
            }
            CP_COMMIT();
            CP_WAIT1();
        } else {
            CP_WAIT0();
        }
        __syncthreads();

        const unsigned* Wst = WsF + st * WSF_STAGE;
        #pragma unroll
        for (int ks = 0; ks < 4; ks++) {
            unsigned a[4];
            a[0] = f2tf(Xs[st][mrow + g][ks * 8 + c]);
            a[1] = f2tf(Xs[st][mrow + g + 8][ks * 8 + c]);
            a[2] = f2tf(Xs[st][mrow + g][ks * 8 + c + 4]);
            a[3] = f2tf(Xs[st][mrow + g + 8][ks * 8 + c + 4]);
            #pragma unroll
            for (int w = 0; w < 3; w++) {
                #pragma unroll
                for (int nt = 0; nt < 4; nt++) {
                    const int ntg = nh * 4 + nt;
                    const uint2 bp = *(const uint2*)&Wst[(w * 32 + ks * 8 + ntg) * 64 + lane * 2];
                    unsigned b[2] = { bp.x, bp.y };
                    mma_tf32(acc[w][nt], a, b);
                }
            }
        }
        __syncthreads();
    }

    // epilogue: store all three projections as tf32 bits (Q pre-scaled 1/8)
    #pragma unroll
    for (int w = 0; w < 3; w++) {
        unsigned* out = (w == 0) ? g_Qt : (w == 1) ? g_Kt : g_Vt;
        const float sc = (w == 0) ? 0.125f : 1.0f;
        #pragma unroll
        for (int nt = 0; nt < 4; nt++) {
            const int ntg = nh * 4 + nt;
            uint2 lo; lo.x = f2tf(acc[w][nt][0] * sc); lo.y = f2tf(acc[w][nt][1] * sc);
            uint2 hi; hi.x = f2tf(acc[w][nt][2] * sc); hi.y = f2tf(acc[w][nt][3] * sc);
            *(uint2*)&out[(size_t)(row0 + mrow + g)     * HEAD + ntg * 8 + 2 * c] = lo;
            *(uint2*)&out[(size_t)(row0 + mrow + g + 8) * HEAD + ntg * 8 + 2 * c] = hi;
        }
    }
}

// ---------------------------------------------------------------------------
// Kernel 2: fused causal flash attention — EXACT R14 champion body:
// static smem, per-tile cp.async + wait0, 3 syncs, P through Ks buffer.
// ---------------------------------------------------------------------------
__global__ __launch_bounds__(128)
void attn_kernel()
{
    __shared__ unsigned Ks[64][68];   // K tf32 bits; P tf32 bits after scores
    __shared__ unsigned Vs[64][72];   // V tf32 bits

    const int tid  = threadIdx.x;
    const int warp = tid >> 5;
    const int lane = tid & 31;
    const int g    = lane >> 2;
    const int c    = lane & 3;

    const int qt   = (NQT2 - 1) - (blockIdx.x >> 1);   // heavy-first
    const int half = blockIdx.x & 1;
    const int b    = blockIdx.y;
    const size_t base = (size_t)b * SEQ * HEAD;
    const int qg0   = qt * BQ;
    const int qrow0 = qg0 + 16 * warp;

    const int nkt  = qt + 1;
    const int h    = (nkt + 1) >> 1;
    const int ktlo = half ? h : 0;
    const int kthi = half ? nkt : h;

    const unsigned* Qsrc = g_Qt + base;
    const unsigned* Ksrc = g_Kt + base;
    const unsigned* Vsrc = g_Vt + base;

    unsigned Qf[8][4];
    #pragma unroll
    for (int ks = 0; ks < 8; ks++) {
        Qf[ks][0] = Qsrc[(size_t)(qrow0 + g)     * HEAD + ks * 8 + c];
        Qf[ks][1] = Qsrc[(size_t)(qrow0 + g + 8) * HEAD + ks * 8 + c];
        Qf[ks][2] = Qsrc[(size_t)(qrow0 + g)     * HEAD + ks * 8 + c + 4];
        Qf[ks][3] = Qsrc[(size_t)(qrow0 + g + 8) * HEAD + ks * 8 + c + 4];
    }

    float O[8][4];
    #pragma unroll
    for (int nt = 0; nt < 8; nt++)
        #pragma unroll
        for (int j = 0; j < 4; j++) O[nt][j] = 0.0f;
    float mrun[2] = { NEG_BIG, NEG_BIG };
    float lrun[2] = { 0.0f, 0.0f };

    #pragma unroll 1
    for (int kt = ktlo; kt < kthi; kt++) {
        const int k0 = kt * TK;
        __syncthreads();   // sync_a: prev PV done reading Ks(P)/Vs

        #pragma unroll
        for (int it = 0; it < 8; it++) {
            const int idx = tid + it * 128;
            const int key = idx >> 4;
            const int d4  = idx & 15;
            cp16(&Ks[key][d4 * 4], &Ksrc[(size_t)(k0 + key) * HEAD + d4 * 4]);
            cp16(&Vs[key][d4 * 4], &Vsrc[(size_t)(k0 + key) * HEAD + d4 * 4]);
        }
        CP_COMMIT();
        CP_WAIT0();
        __syncthreads();   // sync_b: tiles ready

        // ---- scores ----
        float S[8][4];
        #pragma unroll
        for (int nt = 0; nt < 8; nt++)
            #pragma unroll
            for (int j = 0; j < 4; j++) S[nt][j] = 0.0f;

        #pragma unroll
        for (int ks = 0; ks < 8; ks++) {
            #pragma unroll
            for (int nt = 0; nt < 8; nt++) {
                unsigned bf[2];
                bf[0] = Ks[nt * 8 + g][ks * 8 + c];
                bf[1] = Ks[nt * 8 + g][ks * 8 + c + 4];
                mma_tf32(S[nt], Qf[ks], bf);
            }
        }

        // causal mask (diagonal tile)
        if (kt == qt) {
            #pragma unroll
            for (int nt = 0; nt < 8; nt++)
                #pragma unroll
                for (int j = 0; j < 4; j++) {
                    const int col = k0 + nt * 8 + 2 * c + (j & 1);
                    const int row = qrow0 + g + ((j >= 2) ? 8 : 0);
                    if (col > row) S[nt][j] = NEG_BIG;
                }
        }

        // ---- online softmax (rows g, g+8) ----
        float mx0 = NEG_BIG, mx1 = NEG_BIG;
        #pragma unroll
        for (int nt = 0; nt < 8; nt++) {
            mx0 = fmaxf(mx0, fmaxf(S[nt][0], S[nt][1]));
            mx1 = fmaxf(mx1, fmaxf(S[nt][2], S[nt][3]));
        }
        mx0 = fmaxf(mx0, __shfl_xor_sync(0xffffffffu, mx0, 1));
        mx0 = fmaxf(mx0, __shfl_xor_sync(0xffffffffu, mx0, 2));
        mx1 = fmaxf(mx1, __shfl_xor_sync(0xffffffffu, mx1, 1));
        mx1 = fmaxf(mx1, __shfl_xor_sync(0xffffffffu, mx1, 2));

        const float mn0 = fmaxf(mrun[0], mx0);
        const float mn1 = fmaxf(mrun[1], mx1);
        const float al0 = __expf(mrun[0] - mn0);
        const float al1 = __expf(mrun[1] - mn1);

        float ps0 = 0.0f, ps1 = 0.0f;
        #pragma unroll
        for (int nt = 0; nt < 8; nt++) {
            float p0 = __uint_as_float(f2tf(__expf(S[nt][0] - mn0)));
            float p1 = __uint_as_float(f2tf(__expf(S[nt][1] - mn0)));
            float p2 = __uint_as_float(f2tf(__expf(S[nt][2] - mn1)));
            float p3 = __uint_as_float(f2tf(__expf(S[nt][3] - mn1)));
            S[nt][0] = p0; S[nt][1] = p1; S[nt][2] = p2; S[nt][3] = p3;
            ps0 += p0 + p1;
            ps1 += p2 + p3;
        }
        ps0 += __shfl_xor_sync(0xffffffffu, ps0, 1);
        ps0 += __shfl_xor_sync(0xffffffffu, ps0, 2);
        ps1 += __shfl_xor_sync(0xffffffffu, ps1, 1);
        ps1 += __shfl_xor_sync(0xffffffffu, ps1, 2);

        lrun[0] = lrun[0] * al0 + ps0;
        lrun[1] = lrun[1] * al1 + ps1;
        mrun[0] = mn0;
        mrun[1] = mn1;
        #pragma unroll
        for (int nt = 0; nt < 8; nt++) {
            O[nt][0] *= al0; O[nt][1] *= al0;
            O[nt][2] *= al1; O[nt][3] *= al1;
        }

        __syncthreads();   // sync_c: all warps done reading K before P overwrite

        #pragma unroll
        for (int nt = 0; nt < 8; nt++) {
            uint2 lo; lo.x = __float_as_uint(S[nt][0]); lo.y = __float_as_uint(S[nt][1]);
            uint2 hi; hi.x = __float_as_uint(S[nt][2]); hi.y = __float_as_uint(S[nt][3]);
            *(uint2*)&Ks[16 * warp + g][nt * 8 + 2 * c]     = lo;
            *(uint2*)&Ks[16 * warp + g + 8][nt * 8 + 2 * c] = hi;
        }
        __syncwarp();

        // ---- PV ----
        #pragma unroll
        for (int kp = 0; kp < 8; kp++) {
            unsigned a[4];
            a[0] = Ks[16 * warp + g][kp * 8 + c];
            a[1] = Ks[16 * warp + g + 8][kp * 8 + c];
            a[2] = Ks[16 * warp + g][kp * 8 + c + 4];
            a[3] = Ks[16 * warp + g + 8][kp * 8 + c + 4];
            #pragma unroll
            for (int nt = 0; nt < 8; nt++) {
                unsigned bf[2];
                bf[0] = Vs[kp * 8 + c][nt * 8 + g];
                bf[1] = Vs[kp * 8 + c + 4][nt * 8 + g];
                mma_tf32(O[nt], a, bf);
            }
        }
    }

    // epilogue: write unnormalized partials + m,l for this half
    float* Op = g_Op[half];
    #pragma unroll
    for (int nt = 0; nt < 8; nt++) {
        float2 lo; lo.x = O[nt][0]; lo.y = O[nt][1];
        float2 hi; hi.x = O[nt][2]; hi.y = O[nt][3];
        *(float2*)&Op[base + (size_t)(qrow0 + g)     * HEAD + nt * 8 + 2 * c] = lo;
        *(float2*)&Op[base + (size_t)(qrow0 + g + 8) * HEAD + nt * 8 + 2 * c] = hi;
    }
    if (c == 0) {
        const int rg = b * SEQ + qrow0 + g;
        g_m[half][rg]     = mrun[0];
        g_l[half][rg]     = lrun[0];
        g_m[half][rg + 8] = mrun[1];
        g_l[half][rg + 8] = lrun[1];
    }
}

// ---------------------------------------------------------------------------
// Kernel 3: split-K combine — one float4 triple per thread (262K threads,
// latency hidden by parallelism).  Per-element arithmetic identical.
// ---------------------------------------------------------------------------
__global__ __launch_bounds__(256)
void combine_kernel(float* __restrict__ z)
{
    const int t  = blockIdx.x * 256 + threadIdx.x;   // 0 .. MROWS*16-1
    const int r  = t >> 4;
    const int d4 = t & 15;

    const float m0 = g_m[0][r], m1 = g_m[1][r];
    const float l0 = g_l[0][r], l1 = g_l[1][r];
    const float M  = fmaxf(m0, m1);
    const float w0 = __expf(m0 - M);
    const float w1 = __expf(m1 - M);
    const float inv = 1.0f / (l0 * w0 + l1 * w1);

    const size_t idx = (size_t)r * HEAD + d4 * 4;
    float4 a  = *(const float4*)&g_Op[0][idx];
    float4 bq = *(const float4*)&g_Op[1][idx];
    float4 o;
    o.x = (a.x * w0 + bq.x * w1) * inv;
    o.y = (a.y * w0 + bq.y * w1) * inv;
    o.z = (a.z * w0 + bq.z * w1) * inv;
    o.w = (a.w * w0 + bq.w * w1) * inv;
    *(float4*)&z[idx] = o;
}

// ---------------------------------------------------------------------------
extern "C" void kernel_launch(void* const* d_in, const int* in_sizes, int n_in,
                              void* d_out, int out_size)
{
    const float* x  = (const float*)d_in[0];
    const float* Wk = (const float*)d_in[1];
    const float* Wq = (const float*)d_in[2];
    const float* Wv = (const float*)d_in[3];
    float* z = (float*)d_out;
    (void)in_sizes; (void)n_in; (void)out_size;

    // opt-in to >48KB dynamic smem for proj (idempotent; capture-legal)
    cudaFuncSetAttribute(proj_kernel,
                         cudaFuncAttributeMaxDynamicSharedMemorySize,
                         PROJ_SMEM_BYTES);

    wconv_kernel<<<768, 256>>>(Wq, Wk, Wv);

    proj_kernel<<<MROWS / 64, 256, PROJ_SMEM_BYTES>>>(x);

    dim3 agrid(2 * NQT2, BATCH);
    attn_kernel<<<agrid, 128>>>();

    combine_kernel<<<MROWS * 16 / 256, 256>>>(z);
}